// round 2
// baseline (speedup 1.0000x reference)
#include <cuda_runtime.h>
#include <cstdint>

// Problem shape (fixed per reference):
//   x   : [16384, 64, 128] f32
//   sidx: [16384]           int32 or int64 (detected at runtime)
//   W   : [8, 128, 128]     f32
//   out : [16384, 64, 128]  f32
// out[n,m,q] = sum_d x[n,m,d] * W[sidx[n],d,q]

#define NSAMP  16384
#define NCOMP  64
#define DIN    128
#define DOUT   128

using ull = unsigned long long;

// Decoded, clamped species indices (scratch: __device__ global, no alloc).
__device__ int g_sidx[NSAMP];

__device__ __forceinline__ ull ffma2(ull a, ull b, ull c) {
    ull d;
    asm("fma.rn.f32x2 %0, %1, %2, %3;" : "=l"(d) : "l"(a), "l"(b), "l"(c));
    return d;
}

__device__ __forceinline__ ull bcast2(float a) {
    ull d;
    asm("mov.b64 %0, {%1, %1};" : "=l"(d) : "r"(__float_as_uint(a)));
    return d;
}

// ---------------------------------------------------------------------------
// Pre-kernel: detect int32 vs int64 layout of the species index buffer and
// decode into g_sidx. Single block. Only reads the first 16384 32-bit words
// for detection (always in-bounds for either dtype); reads further words
// only once int64 layout is established (buffer is then 32768 words).
// Detection: values are uniform in [0,8). If the buffer is little-endian
// int64, every odd 32-bit word is a high half == 0. A random int32 buffer
// of 16384 values in [0,8) has all-odd-words-zero with probability ~0.
// ---------------------------------------------------------------------------
__global__ void decode_sidx_kernel(const unsigned int* __restrict__ raw)
{
    __shared__ int s_not64;
    const int tid = threadIdx.x;            // 256 threads
    if (tid == 0) s_not64 = 0;
    __syncthreads();

    // Phase 1: detection over words 0..16383 (odd positions).
    int bad = 0;
    for (int w = tid * 2 + 1; w < NSAMP; w += 512) {
        if (raw[w] != 0u) bad = 1;
    }
    if (bad) atomicOr(&s_not64, 1);
    __syncthreads();

    const bool is64 = (s_not64 == 0);

    // Phase 2: decode + clamp.
    for (int i = tid; i < NSAMP; i += 256) {
        unsigned int v = is64 ? raw[2 * i] : raw[i];
        if (v > 7u) v = 7u;                 // never fault, even if model is wrong
        g_sidx[i] = (int)v;
    }
}

__global__ __launch_bounds__(256, 2)
void combine_grouped_gemm_kernel(const float* __restrict__ x,
                                 const float* __restrict__ W,
                                 float* __restrict__ out)
{
    extern __shared__ float smem[];
    float* xs = smem;                 // [64][128]  = 32 KB
    float* ws = smem + NCOMP * DIN;   // [128][128] = 64 KB

    const int n   = blockIdx.x;
    const int tid = threadIdx.x;

    const int s = g_sidx[n];

    // ---- stage x[n] (2048 float4) and W[s] (4096 float4) into smem ----
    {
        const float4* xg  = (const float4*)(x + (size_t)n * (NCOMP * DIN));
        float4*       xs4 = (float4*)xs;
        #pragma unroll
        for (int i = 0; i < (NCOMP * DIN / 4) / 256; i++)      // 8 iters
            xs4[tid + i * 256] = xg[tid + i * 256];

        const float4* wg  = (const float4*)(W + (size_t)s * (DIN * DOUT));
        float4*       ws4 = (float4*)ws;
        #pragma unroll
        for (int i = 0; i < (DIN * DOUT / 4) / 256; i++)       // 16 iters
            ws4[tid + i * 256] = wg[tid + i * 256];
    }
    __syncthreads();

    // ---- 16x16 thread grid; each thread owns a 4(m) x 8(q) output tile ----
    const int tm = tid >> 4;          // 0..15
    const int tq = tid & 15;          // 0..15
    const int m0 = tm * 4;
    const int q0 = tq * 8;

    // accumulators: 4 m-rows x 4 packed q-pairs (f32x2)
    ull acc[4][4];
    #pragma unroll
    for (int i = 0; i < 4; i++)
        #pragma unroll
        for (int j = 0; j < 4; j++)
            acc[i][j] = 0ull;         // bit pattern of {0.0f, 0.0f}

    const float* xrow = xs + m0 * DIN;

    #pragma unroll 2
    for (int k0 = 0; k0 < DIN; k0 += 4) {
        // x[m0..m0+3][k0..k0+3] : 4 x LDS.128
        float4 a4[4];
        #pragma unroll
        for (int i = 0; i < 4; i++)
            a4[i] = *(const float4*)(xrow + i * DIN + k0);

        #pragma unroll
        for (int kk = 0; kk < 4; kk++) {
            // W[k][q0..q0+7] as 4 packed f32x2 (2 x LDS.128, no repack movs)
            const ulonglong2* wrow =
                (const ulonglong2*)(ws + (k0 + kk) * DOUT + q0);
            const ulonglong2 b01 = wrow[0];
            const ulonglong2 b23 = wrow[1];
            ull b[4];
            b[0] = b01.x; b[1] = b01.y; b[2] = b23.x; b[3] = b23.y;

            #pragma unroll
            for (int i = 0; i < 4; i++) {
                const float* ap = (const float*)&a4[i];
                const ull a2 = bcast2(ap[kk]);
                #pragma unroll
                for (int j = 0; j < 4; j++)
                    acc[i][j] = ffma2(a2, b[j], acc[i][j]);
            }
        }
    }

    // ---- epilogue: 4 rows x 8 floats, two STG.128 per row ----
    float* obase = out + (size_t)n * (NCOMP * DOUT) + m0 * DOUT + q0;
    #pragma unroll
    for (int i = 0; i < 4; i++) {
        float2 p0 = reinterpret_cast<float2&>(acc[i][0]);
        float2 p1 = reinterpret_cast<float2&>(acc[i][1]);
        float2 p2 = reinterpret_cast<float2&>(acc[i][2]);
        float2 p3 = reinterpret_cast<float2&>(acc[i][3]);
        float4* op = (float4*)(obase + i * DOUT);
        op[0] = make_float4(p0.x, p0.y, p1.x, p1.y);
        op[1] = make_float4(p2.x, p2.y, p3.x, p3.y);
    }
}

extern "C" void kernel_launch(void* const* d_in, const int* in_sizes, int n_in,
                              void* d_out, int out_size)
{
    // Identify inputs by element count (ordering-proof).
    const float*        x    = nullptr;
    const unsigned int* sidx = nullptr;
    const float*        W    = nullptr;
    for (int i = 0; i < n_in; i++) {
        if      (in_sizes[i] == NSAMP * NCOMP * DIN) x    = (const float*)d_in[i];
        else if (in_sizes[i] == NSAMP)               sidx = (const unsigned int*)d_in[i];
        else if (in_sizes[i] == 8 * DIN * DOUT)      W    = (const float*)d_in[i];
    }
    float* out = (float*)d_out;

    decode_sidx_kernel<<<1, 256>>>(sidx);

    const int smem_bytes = (NCOMP * DIN + DIN * DOUT) * (int)sizeof(float); // 96 KB
    cudaFuncSetAttribute(combine_grouped_gemm_kernel,
                         cudaFuncAttributeMaxDynamicSharedMemorySize, smem_bytes);

    combine_grouped_gemm_kernel<<<NSAMP, 256, smem_bytes>>>(x, W, out);
}

// round 3
// speedup vs baseline: 1.5276x; 1.5276x over previous
#include <cuda_runtime.h>
#include <cstdint>

// Problem shape (fixed per reference):
//   x   : [16384, 64, 128] f32
//   sidx: [16384]           int32 or int64 (detected at runtime)
//   W   : [8, 128, 128]     f32
//   out : [16384, 64, 128]  f32
// out[n,m,q] = sum_d x[n,m,d] * W[sidx[n],d,q]

#define NSAMP  16384
#define NCOMP  64
#define DIN    128
#define DOUT   128

using ull = unsigned long long;

// Decoded, clamped species indices (scratch: __device__ global, no alloc).
__device__ int g_sidx[NSAMP];

__device__ __forceinline__ ull ffma2(ull a, ull b, ull c) {
    ull d;
    asm("fma.rn.f32x2 %0, %1, %2, %3;" : "=l"(d) : "l"(a), "l"(b), "l"(c));
    return d;
}

__device__ __forceinline__ ull bcast2(float a) {
    ull d;
    asm("mov.b64 %0, {%1, %1};" : "=l"(d) : "r"(__float_as_uint(a)));
    return d;
}

// ---------------------------------------------------------------------------
// Pre-kernel: detect int32 vs int64 layout of the species index buffer and
// decode into g_sidx (proven correct in R2: rel_err == 0).
// ---------------------------------------------------------------------------
__global__ void decode_sidx_kernel(const unsigned int* __restrict__ raw)
{
    __shared__ int s_not64;
    const int tid = threadIdx.x;            // 256 threads
    if (tid == 0) s_not64 = 0;
    __syncthreads();

    int bad = 0;
    for (int w = tid * 2 + 1; w < NSAMP; w += 512)
        if (raw[w] != 0u) bad = 1;
    if (bad) atomicOr(&s_not64, 1);
    __syncthreads();

    const bool is64 = (s_not64 == 0);
    for (int i = tid; i < NSAMP; i += 256) {
        unsigned int v = is64 ? raw[2 * i] : raw[i];
        if (v > 7u) v = 7u;
        g_sidx[i] = (int)v;
    }
}

// ---------------------------------------------------------------------------
// Main kernel: 128 threads/CTA, each thread computes an 8(m) x 8(q) tile.
// Thread map: tq = tid & 15 (q0 = 8*tq), tm = tid >> 4 (m0 = 8*tm).
// Within a warp: 16 q-lanes x 2 m-lanes -> x LDS are 2-address broadcasts,
// W LDS are 512B-contiguous conflict-free.
// ---------------------------------------------------------------------------
__global__ __launch_bounds__(128, 2)
void combine_grouped_gemm_kernel(const float* __restrict__ x,
                                 const float* __restrict__ W,
                                 float* __restrict__ out)
{
    extern __shared__ float smem[];
    float* xs = smem;                 // [64][128]  = 32 KB
    float* ws = smem + NCOMP * DIN;   // [128][128] = 64 KB

    const int n   = blockIdx.x;
    const int tid = threadIdx.x;      // 0..127
    const int s   = g_sidx[n];

    // ---- stage x[n] (2048 float4) and W[s] (4096 float4) into smem ----
    {
        const float4* xg  = (const float4*)(x + (size_t)n * (NCOMP * DIN));
        float4*       xs4 = (float4*)xs;
        #pragma unroll
        for (int i = 0; i < (NCOMP * DIN / 4) / 128; i++)      // 16 iters
            xs4[tid + i * 128] = xg[tid + i * 128];

        const float4* wg  = (const float4*)(W + (size_t)s * (DIN * DOUT));
        float4*       ws4 = (float4*)ws;
        #pragma unroll
        for (int i = 0; i < (DIN * DOUT / 4) / 128; i++)       // 32 iters
            ws4[tid + i * 128] = wg[tid + i * 128];
    }
    __syncthreads();

    const int tq = tid & 15;          // 0..15
    const int tm = tid >> 4;          // 0..7
    const int m0 = tm * 8;
    const int q0 = tq * 8;

    // accumulators: 8 m-rows x 4 packed q-pairs (f32x2) = 64 registers
    ull acc[8][4];
    #pragma unroll
    for (int i = 0; i < 8; i++)
        #pragma unroll
        for (int j = 0; j < 4; j++)
            acc[i][j] = 0ull;

    const float* xrow = xs + m0 * DIN;

    #pragma unroll 2
    for (int k0 = 0; k0 < DIN; k0 += 4) {
        // x[m0..m0+7][k0..k0+3] : 8 x LDS.128 (2 distinct addrs per warp)
        float4 a4[8];
        #pragma unroll
        for (int i = 0; i < 8; i++)
            a4[i] = *(const float4*)(xrow + i * DIN + k0);

        #pragma unroll
        for (int kk = 0; kk < 4; kk++) {
            // W[k][q0..q0+7] : 2 x LDS.128 as packed f32x2
            const ulonglong2* wrow =
                (const ulonglong2*)(ws + (k0 + kk) * DOUT + q0);
            const ulonglong2 b01 = wrow[0];
            const ulonglong2 b23 = wrow[1];
            ull b[4];
            b[0] = b01.x; b[1] = b01.y; b[2] = b23.x; b[3] = b23.y;

            #pragma unroll
            for (int i = 0; i < 8; i++) {
                const float* ap = (const float*)&a4[i];
                const ull a2 = bcast2(ap[kk]);
                #pragma unroll
                for (int j = 0; j < 4; j++)
                    acc[i][j] = ffma2(a2, b[j], acc[i][j]);
            }
        }
    }

    // ---- epilogue: 8 rows x 8 floats, two STG.128 per row ----
    float* obase = out + (size_t)n * (NCOMP * DOUT) + m0 * DOUT + q0;
    #pragma unroll
    for (int i = 0; i < 8; i++) {
        float2 p0 = reinterpret_cast<float2&>(acc[i][0]);
        float2 p1 = reinterpret_cast<float2&>(acc[i][1]);
        float2 p2 = reinterpret_cast<float2&>(acc[i][2]);
        float2 p3 = reinterpret_cast<float2&>(acc[i][3]);
        float4* op = (float4*)(obase + i * DOUT);
        op[0] = make_float4(p0.x, p0.y, p1.x, p1.y);
        op[1] = make_float4(p2.x, p2.y, p3.x, p3.y);
    }
}

extern "C" void kernel_launch(void* const* d_in, const int* in_sizes, int n_in,
                              void* d_out, int out_size)
{
    // Identify inputs by element count (ordering-proof).
    const float*        x    = nullptr;
    const unsigned int* sidx = nullptr;
    const float*        W    = nullptr;
    for (int i = 0; i < n_in; i++) {
        if      (in_sizes[i] == NSAMP * NCOMP * DIN) x    = (const float*)d_in[i];
        else if (in_sizes[i] == NSAMP)               sidx = (const unsigned int*)d_in[i];
        else if (in_sizes[i] == 8 * DIN * DOUT)      W    = (const float*)d_in[i];
    }
    float* out = (float*)d_out;

    decode_sidx_kernel<<<1, 256>>>(sidx);

    const int smem_bytes = (NCOMP * DIN + DIN * DOUT) * (int)sizeof(float); // 96 KB
    cudaFuncSetAttribute(combine_grouped_gemm_kernel,
                         cudaFuncAttributeMaxDynamicSharedMemorySize, smem_bytes);

    combine_grouped_gemm_kernel<<<NSAMP, 128, smem_bytes>>>(x, W, out);
}

// round 6
// speedup vs baseline: 3.5768x; 2.3415x over previous
#include <cuda_runtime.h>
#include <cstdint>

// out[n,m,q] = sum_d x[n,m,d] * W[sidx[n],d,q]
// x: [16384,64,128] f32, sidx: [16384] i32/i64, W: [8,128,128] f32
// Route: species-grouped persistent CTAs + legacy mma.sync.m16n8k16 bf16
// with 3-term fp32 emulation (xhi*Whi + xhi*Wlo + xlo*Whi).

#define NSAMP  16384
#define NCOMP  64
#define DIN    128
#define DOUT   128
#define NSPEC  8
#define SLOTS  19
#define GRIDSZ (NSPEC * SLOTS)     // 152 = GB300 SM count

#define KPAD   136                 // padded k-stride (bank-rotation 4i mod 32)
#define WELEMS (DOUT * KPAD)       // 17408 bf16 per W image

// ---------------- device scratch ----------------
__device__ int g_sidx[NSAMP];
__device__ int g_cnt[NSPEC];
__device__ int g_off[NSPEC];
__device__ int g_fill[NSPEC];
__device__ int g_sorted[NSAMP];
__device__ int g_is64;
__device__ __align__(16) uint16_t g_whi[NSPEC][WELEMS];  // Wt[q][k] bf16 hi
__device__ __align__(16) uint16_t g_wlo[NSPEC][WELEMS];  // Wt[q][k] bf16 lo

// ---------------- smem layout (bytes) ----------------
#define SM_WHI  0
#define SM_WLO  (SM_WHI + WELEMS * 2)          // 34816
#define SM_XHI  (SM_WLO + WELEMS * 2)          // 69632
#define SM_XLO  (SM_XHI + NCOMP * KPAD * 2)    // 87040
#define SM_RAW0 (SM_XLO + NCOMP * KPAD * 2)    // 104448
#define SM_RAW1 (SM_RAW0 + 32768)              // 137216
#define SM_TOTAL (SM_RAW1 + 32768)             // 169984

// ---------------- PTX helpers ----------------
__device__ __forceinline__ uint32_t smem_u32(const void* p) {
    uint32_t a;
    asm("{ .reg .u64 t; cvta.to.shared.u64 t, %1; cvt.u32.u64 %0, t; }"
        : "=r"(a) : "l"(p));
    return a;
}
__device__ __forceinline__ void cp16(uint32_t dst, const void* src) {
    asm volatile("cp.async.cg.shared.global [%0], [%1], 16;"
                 :: "r"(dst), "l"(src) : "memory");
}
__device__ __forceinline__ void cp_commit() {
    asm volatile("cp.async.commit_group;" ::: "memory");
}
__device__ __forceinline__ void cp_wait0() {
    asm volatile("cp.async.wait_group 0;" ::: "memory");
}
__device__ __forceinline__ void cp_wait1() {
    asm volatile("cp.async.wait_group 1;" ::: "memory");
}
__device__ __forceinline__ void ldsm4(uint32_t* r, uint32_t addr) {
    asm volatile("ldmatrix.sync.aligned.m8n8.x4.shared.b16 {%0,%1,%2,%3}, [%4];"
                 : "=r"(r[0]), "=r"(r[1]), "=r"(r[2]), "=r"(r[3]) : "r"(addr));
}
__device__ __forceinline__ void mma_bf16(float* d, const uint32_t* a,
                                         const uint32_t* b) {
    asm volatile(
        "mma.sync.aligned.m16n8k16.row.col.f32.bf16.bf16.f32 "
        "{%0,%1,%2,%3}, {%4,%5,%6,%7}, {%8,%9}, {%0,%1,%2,%3};"
        : "+f"(d[0]), "+f"(d[1]), "+f"(d[2]), "+f"(d[3])
        : "r"(a[0]), "r"(a[1]), "r"(a[2]), "r"(a[3]), "r"(b[0]), "r"(b[1]));
}
// pack {hi half = fh, lo half = fl} as bf16x2
__device__ __forceinline__ uint32_t pack_bf16x2(float fh, float fl) {
    uint32_t r;
    asm("cvt.rn.bf16x2.f32 %0, %1, %2;" : "=r"(r) : "f"(fh), "f"(fl));
    return r;
}

// ---------------- prep kernels (decode/group: proven in R2/R3) ----------------
__global__ void prep0_detect(const unsigned int* __restrict__ raw) {
    __shared__ int s_not64;
    int tid = threadIdx.x;
    if (tid == 0) s_not64 = 0;
    if (tid < NSPEC) { g_cnt[tid] = 0; g_fill[tid] = 0; }
    __syncthreads();
    int bad = 0;
    for (int w = tid * 2 + 1; w < NSAMP; w += 512)
        if (raw[w] != 0u) bad = 1;
    if (bad) atomicOr(&s_not64, 1);
    __syncthreads();
    if (tid == 0) g_is64 = (s_not64 == 0);
}
__global__ void prep1_decode_count(const unsigned int* __restrict__ raw) {
    int i = blockIdx.x * 256 + threadIdx.x;
    unsigned v = g_is64 ? raw[2 * i] : raw[i];
    if (v > 7u) v = 7u;
    g_sidx[i] = (int)v;
    atomicAdd(&g_cnt[v], 1);
}
__global__ void prep2_offsets() {
    int o = 0;
    for (int s = 0; s < NSPEC; s++) { g_off[s] = o; o += g_cnt[s]; }
}
__global__ void prep3_scatter() {
    int n = blockIdx.x * 256 + threadIdx.x;
    int s = g_sidx[n];
    int pos = atomicAdd(&g_fill[s], 1);
    g_sorted[g_off[s] + pos] = n;
}
// Wt[q][k] bf16 hi/lo, padded to KPAD, pads zeroed.
__global__ void prep4_wimg(const float* __restrict__ W) {
    int s = blockIdx.x;
    for (int e = threadIdx.x; e < WELEMS; e += blockDim.x) {
        int q = e / KPAD, k = e % KPAD;
        uint16_t hb = 0, lb = 0;
        if (k < DIN) {
            float v = W[s * DIN * DOUT + k * DOUT + q];
            // hi = rn(v); lo = rn(v - hi)
            uint32_t p = pack_bf16x2(v, 0.0f);         // hi bits in upper half
            hb = (uint16_t)(p >> 16);
            float hf = __uint_as_float(((uint32_t)hb) << 16);
            uint32_t pl = pack_bf16x2(v - hf, 0.0f);
            lb = (uint16_t)(pl >> 16);
        }
        g_whi[s][q * KPAD + k] = hb;
        g_wlo[s][q * KPAD + k] = lb;
    }
}

// ---------------- main kernel ----------------
__global__ __launch_bounds__(256, 1)
void mma_main(const float* __restrict__ x, float* __restrict__ out)
{
    extern __shared__ char smem[];
    const uint32_t sb = smem_u32(smem);
    const int tid  = threadIdx.x;
    const int lane = tid & 31;
    const int wid  = tid >> 5;
    const int wm   = wid >> 2;           // 0..1  (m tile 32)
    const int wn   = wid & 3;            // 0..3  (n tile 32)
    const int spec = blockIdx.x / SLOTS;
    const int slot = blockIdx.x % SLOTS;

    // ---- stage W images (hi+lo bf16, 68 KB) once ----
    {
        const uint16_t* whi = g_whi[spec];
        const uint16_t* wlo = g_wlo[spec];
        #pragma unroll
        for (int i = 0; i < 9; i++) {
            int idx = tid + i * 256;              // 16B chunks; 2176 total
            if (idx < WELEMS / 8) {
                cp16(sb + SM_WHI + idx * 16, whi + idx * 8);
                cp16(sb + SM_WLO + idx * 16, wlo + idx * 8);
            }
        }
        cp_commit();
    }

    const int cnt = g_cnt[spec];
    const int off = g_off[spec];
    if (slot >= cnt) { cp_wait0(); return; }      // uniform per CTA

    // ldmatrix lane address components (bytes from buffer base)
    // A (x): matrices: (m0-7,k0)(m8-15,k0)(m0-7,k8)(m8-15,k8)
    const int a_row  = (lane & 15);
    const int a_koff = (lane >> 4) * 8;
    // B (Wt): matrices: (n0-7,k0)(n0-7,k8)(n8-15,k0)(n8-15,k8)
    const int b_row  = ((lane >> 4) * 8) + (lane & 7);
    const int b_koff = ((lane >> 3) & 1) * 8;

    uint32_t aAddr[2], bAddr[2];
    #pragma unroll
    for (int mi = 0; mi < 2; mi++)
        aAddr[mi] = sb + SM_XHI +
            ((wm * 32 + mi * 16 + a_row) * KPAD + a_koff) * 2;
    #pragma unroll
    for (int p = 0; p < 2; p++)
        bAddr[p] = sb + SM_WHI +
            ((wn * 32 + p * 16 + b_row) * KPAD + b_koff) * 2;

    const uint32_t XLO_OFF = SM_XLO - SM_XHI;     // 17408
    const uint32_t WLO_OFF = SM_WLO - SM_WHI;     // 34816

    // ---- prefetch first sample ----
    int n_cur = g_sorted[off + slot];
    {
        const float* xs = x + (size_t)n_cur * (NCOMP * DIN);
        #pragma unroll
        for (int i = 0; i < 8; i++)
            cp16(sb + SM_RAW0 + (tid + i * 256) * 16, xs + (tid + i * 256) * 4);
        cp_commit();
    }

    int buf = 0;
    for (int j = slot; j < cnt; j += SLOTS) {
        // prefetch next (dummy refetch of current on last iter)
        const int jn = j + SLOTS;
        const int n_next = (jn < cnt) ? g_sorted[off + jn] : n_cur;
        {
            const uint32_t dst = sb + (buf ? SM_RAW0 : SM_RAW1);
            const float* xs = x + (size_t)n_next * (NCOMP * DIN);
            #pragma unroll
            for (int i = 0; i < 8; i++)
                cp16(dst + (tid + i * 256) * 16, xs + (tid + i * 256) * 4);
            cp_commit();
        }
        cp_wait1();                   // current raw buffer ready
        __syncthreads();              // prev mma done before overwriting xhi/xlo

        // ---- convert raw fp32 -> bf16 hi/lo (conflict-free) ----
        {
            const float* rawf = (const float*)(smem + (buf ? SM_RAW1 : SM_RAW0));
            #pragma unroll
            for (int jj = 0; jj < 8; jj++) {
                const int f   = jj * 1024 + tid * 4;
                const int row = f >> 7;           // 8*jj + (tid>>5)
                const int k   = f & 127;          // 4*(tid&31)
                float4 v = *(const float4*)(rawf + f);

                uint32_t h01 = pack_bf16x2(v.y, v.x);
                uint32_t h23 = pack_bf16x2(v.w, v.z);
                float h0 = __uint_as_float(h01 << 16);
                float h1 = __uint_as_float(h01 & 0xFFFF0000u);
                float h2 = __uint_as_float(h23 << 16);
                float h3 = __uint_as_float(h23 & 0xFFFF0000u);
                uint32_t l01 = pack_bf16x2(v.y - h1, v.x - h0);
                uint32_t l23 = pack_bf16x2(v.w - h3, v.z - h2);

                const int boff = (row * KPAD + k) * 2;
                *(uint2*)(smem + SM_XHI + boff) = make_uint2(h01, h23);
                *(uint2*)(smem + SM_XLO + boff) = make_uint2(l01, l23);
            }
        }
        __syncthreads();

        // ---- 3-term bf16 mma: acc = xhi*Whi + xhi*Wlo + xlo*Whi ----
        float acc[2][4][4];
        #pragma unroll
        for (int mi = 0; mi < 2; mi++)
            #pragma unroll
            for (int ni = 0; ni < 4; ni++)
                #pragma unroll
                for (int e = 0; e < 4; e++) acc[mi][ni][e] = 0.0f;

        #pragma unroll
        for (int ks = 0; ks < 8; ks++) {
            const uint32_t kb = ks * 32;          // 16 bf16 * 2B
            uint32_t AH[2][4], AL[2][4], BH[2][4], BL[2][4];
            #pragma unroll
            for (int mi = 0; mi < 2; mi++) {
                ldsm4(AH[mi], aAddr[mi] + kb);
                ldsm4(AL[mi], aAddr[mi] + XLO_OFF + kb);
            }
            #pragma unroll
            for (int p = 0; p < 2; p++) {
                ldsm4(BH[p], bAddr[p] + kb);
                ldsm4(BL[p], bAddr[p] + WLO_OFF + kb);
            }
            #pragma unroll
            for (int mi = 0; mi < 2; mi++)
                #pragma unroll
                for (int p = 0; p < 2; p++)
                    #pragma unroll
                    for (int h = 0; h < 2; h++) {
                        const int ni = p * 2 + h;
                        mma_bf16(acc[mi][ni], AH[mi], &BH[p][2 * h]);
                        mma_bf16(acc[mi][ni], AH[mi], &BL[p][2 * h]);
                        mma_bf16(acc[mi][ni], AL[mi], &BH[p][2 * h]);
                    }
        }

        // ---- epilogue: direct STG.64 ----
        {
            const int r  = lane >> 2;
            const int c2 = 2 * (lane & 3);
            float* ob = out + (size_t)n_cur * (NCOMP * DOUT);
            #pragma unroll
            for (int mi = 0; mi < 2; mi++) {
                const int gm = wm * 32 + mi * 16 + r;
                #pragma unroll
                for (int ni = 0; ni < 4; ni++) {
                    const int gq = wn * 32 + ni * 8 + c2;
                    float* o = ob + gm * DOUT + gq;
                    *(float2*)o = make_float2(acc[mi][ni][0], acc[mi][ni][1]);
                    *(float2*)(o + 8 * DOUT) =
                        make_float2(acc[mi][ni][2], acc[mi][ni][3]);
                }
            }
        }

        n_cur = n_next;
        buf ^= 1;
    }
    cp_wait0();
}

// ---------------- launch ----------------
extern "C" void kernel_launch(void* const* d_in, const int* in_sizes, int n_in,
                              void* d_out, int out_size)
{
    const float*        x    = nullptr;
    const unsigned int* sidx = nullptr;
    const float*        W    = nullptr;
    for (int i = 0; i < n_in; i++) {
        if      (in_sizes[i] == NSAMP * NCOMP * DIN) x    = (const float*)d_in[i];
        else if (in_sizes[i] == NSAMP)               sidx = (const unsigned int*)d_in[i];
        else if (in_sizes[i] == NSPEC * DIN * DOUT)  W    = (const float*)d_in[i];
    }
    float* out = (float*)d_out;

    prep0_detect<<<1, 256>>>(sidx);
    prep1_decode_count<<<NSAMP / 256, 256>>>(sidx);
    prep2_offsets<<<1, 1>>>();
    prep3_scatter<<<NSAMP / 256, 256>>>();
    prep4_wimg<<<NSPEC, 256>>>(W);

    cudaFuncSetAttribute(mma_main, cudaFuncAttributeMaxDynamicSharedMemorySize,
                         SM_TOTAL);
    mma_main<<<GRIDSZ, 256, SM_TOTAL>>>(x, out);
}